// round 1
// baseline (speedup 1.0000x reference)
#include <cuda_runtime.h>
#include <cstdint>

#define NE    16
#define NTOK  4096
#define INF   1024
#define OUTF  2048
#define BM    64
#define BN    64
#define BK    16
#define MAXMT (NTOK / BM + NE)   // 80 worst-case m-tiles

// ---- device scratch (no allocations allowed) ----
__device__ int g_counts[NE];
__device__ int g_off[NE + 1];
__device__ int g_fill[NE];
__device__ int g_sorted[NTOK];
__device__ int g_tile[NE + 1];

// ---- 1. init ----
__global__ void k_init() {
    if (threadIdx.x < NE) g_counts[threadIdx.x] = 0;
}

// ---- 2. histogram ----
__global__ void k_hist(const int* __restrict__ gate) {
    int t = blockIdx.x * 256 + threadIdx.x;
    if (t < NTOK) atomicAdd(&g_counts[gate[t]], 1);
}

// ---- 3. scan (tiny: 16 bins, single thread) ----
__global__ void k_scan() {
    if (threadIdx.x == 0) {
        int s = 0, ts = 0;
        for (int e = 0; e < NE; e++) {
            g_off[e] = s;
            g_fill[e] = s;
            g_tile[e] = ts;
            int c = g_counts[e];
            s += c;
            ts += (c + BM - 1) / BM;
        }
        g_off[NE] = s;
        g_tile[NE] = ts;
    }
}

// ---- 4. scatter tokens into expert-sorted order ----
__global__ void k_scatter(const int* __restrict__ gate) {
    int t = blockIdx.x * 256 + threadIdx.x;
    if (t < NTOK) {
        int p = atomicAdd(&g_fill[gate[t]], 1);
        g_sorted[p] = t;
    }
}

// ---- 5. grouped GEMM: out[tok, n] = sum_k x[tok,k] * W[e, n, k] ----
// BM=64 x BN=64 tile, BK=16, 256 threads, 4x4 outputs/thread via fma.rn.f32x2.
// A stored in SMEM as duplicated pairs {a,a} so the compute loop needs no packs.
__global__ __launch_bounds__(256) void k_gemm(
    const float* __restrict__ x,
    const float* __restrict__ w,
    float* __restrict__ out)
{
    const int mt = blockIdx.x;
    if (mt >= g_tile[NE]) return;
    const int n0 = blockIdx.y * BN;

    // flat m-tile -> expert (g_tile is monotone; count boundaries below mt)
    int e = 0;
#pragma unroll
    for (int i = 1; i < NE; i++) e += (mt >= g_tile[i]);

    const int seg_start = g_off[e];
    const int seg_cnt   = g_off[e + 1] - seg_start;
    const int m0        = (mt - g_tile[e]) * BM;

    __shared__ float As2[BK][2 * BM + 4];  // dup pairs, stride 132 floats
    __shared__ float Bs[BK][BN + 4];       // stride 68 floats
    __shared__ int   rowTok[BM];

    const int tid = threadIdx.x;

    if (tid < BM) {
        int idx = m0 + tid;
        rowTok[tid] = (idx < seg_cnt) ? g_sorted[seg_start + idx] : -1;
    }
    __syncthreads();

    // loader mapping: 256 threads -> 64 rows x 4 k-quads (float4 each)
    const int lrow = tid >> 2;          // 0..63
    const int lkq  = (tid & 3) << 2;    // 0,4,8,12

    const int    tokL = rowTok[lrow];
    const float* xb   = (tokL >= 0) ? (x + (size_t)tokL * INF) : nullptr;
    const float* wb   = w + (size_t)e * OUTF * INF + (size_t)(n0 + lrow) * INF;

    // compute mapping: 16x16 thread grid, 4 m x 4 n per thread
    const int tx = tid & 15;   // n quad
    const int ty = tid >> 4;   // m quad

    unsigned long long acc[4][2];
#pragma unroll
    for (int i = 0; i < 4; i++) { acc[i][0] = 0ull; acc[i][1] = 0ull; }

    for (int k0 = 0; k0 < INF; k0 += BK) {
        float4 av = make_float4(0.f, 0.f, 0.f, 0.f);
        if (xb) av = *reinterpret_cast<const float4*>(xb + k0 + lkq);
        float4 bv = *reinterpret_cast<const float4*>(wb + k0 + lkq);

        __syncthreads();   // previous compute done before overwriting smem
#pragma unroll
        for (int j = 0; j < 4; j++) {
            float va = (&av.x)[j];
            unsigned long long pa;
            asm("mov.b64 %0, {%1, %1};" : "=l"(pa) : "f"(va));
            *reinterpret_cast<unsigned long long*>(&As2[lkq + j][2 * lrow]) = pa;
            Bs[lkq + j][lrow] = (&bv.x)[j];
        }
        __syncthreads();

#pragma unroll
        for (int kk = 0; kk < BK; kk++) {
            // a dup-pairs for m = ty*4 + {0,1,2,3}
            ulonglong2 a01 = *reinterpret_cast<const ulonglong2*>(&As2[kk][ty * 8]);
            ulonglong2 a23 = *reinterpret_cast<const ulonglong2*>(&As2[kk][ty * 8 + 4]);
            // b pairs for n = n0 + tx*4 + {0,1} and {2,3}
            ulonglong2 bp  = *reinterpret_cast<const ulonglong2*>(&Bs[kk][tx * 4]);

            asm("fma.rn.f32x2 %0, %1, %2, %0;" : "+l"(acc[0][0]) : "l"(a01.x), "l"(bp.x));
            asm("fma.rn.f32x2 %0, %1, %2, %0;" : "+l"(acc[0][1]) : "l"(a01.x), "l"(bp.y));
            asm("fma.rn.f32x2 %0, %1, %2, %0;" : "+l"(acc[1][0]) : "l"(a01.y), "l"(bp.x));
            asm("fma.rn.f32x2 %0, %1, %2, %0;" : "+l"(acc[1][1]) : "l"(a01.y), "l"(bp.y));
            asm("fma.rn.f32x2 %0, %1, %2, %0;" : "+l"(acc[2][0]) : "l"(a23.x), "l"(bp.x));
            asm("fma.rn.f32x2 %0, %1, %2, %0;" : "+l"(acc[2][1]) : "l"(a23.x), "l"(bp.y));
            asm("fma.rn.f32x2 %0, %1, %2, %0;" : "+l"(acc[3][0]) : "l"(a23.y), "l"(bp.x));
            asm("fma.rn.f32x2 %0, %1, %2, %0;" : "+l"(acc[3][1]) : "l"(a23.y), "l"(bp.y));
        }
    }

    // epilogue: scatter to original token rows
#pragma unroll
    for (int i = 0; i < 4; i++) {
        int m   = ty * 4 + i;
        int tok = rowTok[m];
        if (tok >= 0) {
            float4 o;
            o.x = __uint_as_float((unsigned)(acc[i][0]));
            o.y = __uint_as_float((unsigned)(acc[i][0] >> 32));
            o.z = __uint_as_float((unsigned)(acc[i][1]));
            o.w = __uint_as_float((unsigned)(acc[i][1] >> 32));
            *reinterpret_cast<float4*>(out + (size_t)tok * OUTF + n0 + tx * 4) = o;
        }
    }
}

extern "C" void kernel_launch(void* const* d_in, const int* in_sizes, int n_in,
                              void* d_out, int out_size)
{
    const float* x    = (const float*)d_in[0];
    const int*   gate = (const int*)d_in[1];
    const float* w    = (const float*)d_in[2];
    float*       out  = (float*)d_out;

    k_init<<<1, 32>>>();
    k_hist<<<NTOK / 256, 256>>>(gate);
    k_scan<<<1, 32>>>();
    k_scatter<<<NTOK / 256, 256>>>(gate);

    dim3 grid(MAXMT, OUTF / BN);   // 80 x 32
    k_gemm<<<grid, 256>>>(x, w, out);
}

// round 3
// speedup vs baseline: 4.3922x; 4.3922x over previous
#include <cuda_runtime.h>
#include <cstdint>

#define NE    16
#define NTOK  4096
#define INF   1024
#define OUTF  2048
#define BM    128
#define BN    128
#define BK    32
#define NKI   (INF / BK)          // 32 k-chunks
#define MAXMT (NTOK / BM + NE)    // 48 worst-case m-tiles
#define LDA   36                  // smem row stride in floats (32 + 4 pad)

// ---- device scratch ----
__device__ int   g_counts[NE];
__device__ int   g_off[NE + 1];
__device__ int   g_fill[NE];
__device__ int   g_sorted[NTOK];
__device__ int   g_tile[NE + 1];
__device__ float g_xt[NTOK * INF];   // x rounded to tf32 (16MB)

// ---- routing ----
__global__ void k_init() {
    if (threadIdx.x < NE) g_counts[threadIdx.x] = 0;
}
__global__ void k_hist(const int* __restrict__ gate) {
    int t = blockIdx.x * 256 + threadIdx.x;
    if (t < NTOK) atomicAdd(&g_counts[gate[t]], 1);
}
__global__ void k_scan() {
    if (threadIdx.x == 0) {
        int s = 0, ts = 0;
        for (int e = 0; e < NE; e++) {
            g_off[e] = s; g_fill[e] = s; g_tile[e] = ts;
            int c = g_counts[e];
            s += c; ts += (c + BM - 1) / BM;
        }
        g_off[NE] = s; g_tile[NE] = ts;
    }
}
__global__ void k_scatter(const int* __restrict__ gate) {
    int t = blockIdx.x * 256 + threadIdx.x;
    if (t < NTOK) {
        int p = atomicAdd(&g_fill[gate[t]], 1);
        g_sorted[p] = t;
    }
}

// ---- x -> tf32 (rounded) once ----
__device__ __forceinline__ uint32_t f2tf32(float f) {
    uint32_t r;
    asm("cvt.rna.tf32.f32 %0, %1;" : "=r"(r) : "f"(f));
    return r;
}
__global__ void k_cvtx(const float* __restrict__ x) {
    int i = (blockIdx.x * 256 + threadIdx.x) * 4;
    float4 v = *(const float4*)(x + i);
    uint4 t;
    t.x = f2tf32(v.x); t.y = f2tf32(v.y);
    t.z = f2tf32(v.z); t.w = f2tf32(v.w);
    *(uint4*)(g_xt + i) = t;
}

// ---- async copy helpers (baseline sm_80 ISA) ----
__device__ __forceinline__ uint32_t smem_u32(const void* p) {
    uint32_t a;
    asm("{ .reg .u64 t; cvta.to.shared.u64 t, %1; cvt.u32.u64 %0, t; }" : "=r"(a) : "l"(p));
    return a;
}
__device__ __forceinline__ void cp16(uint32_t dst, const void* src, uint32_t srcsz) {
    asm volatile("cp.async.ca.shared.global [%0], [%1], 16, %2;"
                 :: "r"(dst), "l"(src), "r"(srcsz) : "memory");
}
#define CP_COMMIT() asm volatile("cp.async.commit_group;" ::: "memory")
#define CP_WAIT(n)  asm volatile("cp.async.wait_group %0;" :: "n"(n) : "memory")

__device__ __forceinline__ void mma_tf32(float c[4], const uint32_t a[4], const uint32_t b[2]) {
    asm volatile(
        "mma.sync.aligned.m16n8k8.row.col.f32.tf32.tf32.f32 "
        "{%0,%1,%2,%3}, {%4,%5,%6,%7}, {%8,%9}, {%0,%1,%2,%3};"
        : "+f"(c[0]), "+f"(c[1]), "+f"(c[2]), "+f"(c[3])
        : "r"(a[0]), "r"(a[1]), "r"(a[2]), "r"(a[3]), "r"(b[0]), "r"(b[1]));
}

// SMEM (floats): A buffers at buf*9216, B at 4608 + buf*9216; rowTok at 18432
#define SM_FLOATS  18432
#define SMEM_BYTES (SM_FLOATS * 4 + 512)

// ---- grouped GEMM: out[tok, n] = x[tok,:] . W[e, n, :] ----
__global__ __launch_bounds__(256, 2) void k_gemm(
    const float* __restrict__ w,
    float* __restrict__ out)
{
    const int mt = blockIdx.x;
    if (mt >= g_tile[NE]) return;
    const int n0 = blockIdx.y * BN;

    extern __shared__ float smf[];
    int* rowTok = (int*)(smf + SM_FLOATS);

    const int tid = threadIdx.x;
    const int wid = tid >> 5;
    const int ln  = tid & 31;

    // expert for this m-tile
    int e = 0;
#pragma unroll
    for (int i = 1; i < NE; i++) e += (mt >= g_tile[i]);
    const int seg_start = g_off[e];
    const int seg_cnt   = g_off[e + 1] - seg_start;
    const int m0        = (mt - g_tile[e]) * BM;

    if (tid < BM) {
        int idx = m0 + tid;
        rowTok[tid] = (idx < seg_cnt) ? g_sorted[seg_start + idx] : -1;
    }
    __syncthreads();

    // ---- loader setup: thread handles rows (tid>>3)+32i, 16B unit q=(tid&7) ----
    const int lr = tid >> 3;
    const int lq = tid & 7;
    const float* wbase = w + (size_t)e * OUTF * INF;
    int ltok[4];
    const float* asrc[4];
    const float* bsrc[4];
#pragma unroll
    for (int i = 0; i < 4; i++) {
        int r = lr + 32 * i;
        ltok[i] = rowTok[r];
        asrc[i] = g_xt + (size_t)((ltok[i] < 0) ? 0 : ltok[i]) * INF + lq * 4;
        bsrc[i] = wbase + (size_t)(n0 + r) * INF + lq * 4;
    }
    const uint32_t sbase = smem_u32(smf);
    uint32_t adst[4], bdst[4];
#pragma unroll
    for (int i = 0; i < 4; i++) {
        adst[i] = sbase + ((lr + 32 * i) * LDA + lq * 4) * 4;
        bdst[i] = sbase + (4608 + (lr + 32 * i) * LDA + lq * 4) * 4;
    }

    // ---- compute setup ----
    const int wm = wid >> 2;                 // 0..1
    const int wn = wid & 3;                  // 0..3
    const int aRow = wm * 64 + (ln >> 2);
    const int bRow = wn * 32 + (ln >> 2);
    const int kCol = ln & 3;

    float c[4][4][4];
#pragma unroll
    for (int i = 0; i < 4; i++)
#pragma unroll
        for (int j = 0; j < 4; j++) {
            c[i][j][0] = 0.f; c[i][j][1] = 0.f; c[i][j][2] = 0.f; c[i][j][3] = 0.f;
        }

    // prologue: issue chunk 0 into buffer 0
#pragma unroll
    for (int i = 0; i < 4; i++) {
        cp16(adst[i], asrc[i], ltok[i] < 0 ? 0u : 16u);
        cp16(bdst[i], bsrc[i], 16u);
    }
    CP_COMMIT();

    for (int it = 0; it < NKI; it++) {
        const int cbuf = it & 1;
        if (it + 1 < NKI) {
            const int nb = (it + 1) & 1;
            const int koff = (it + 1) * BK;
#pragma unroll
            for (int i = 0; i < 4; i++) {
                cp16(adst[i] + nb * 9216 * 4, asrc[i] + koff, ltok[i] < 0 ? 0u : 16u);
                cp16(bdst[i] + nb * 9216 * 4, bsrc[i] + koff, 16u);
            }
            CP_COMMIT();
            CP_WAIT(1);
        } else {
            CP_WAIT(0);
        }
        __syncthreads();

        const float* As = smf + cbuf * 9216;
        const float* Bs = smf + 4608 + cbuf * 9216;

#pragma unroll
        for (int ks = 0; ks < 4; ks++) {
            uint32_t a[4][4], b[4][2];
#pragma unroll
            for (int mtl = 0; mtl < 4; mtl++) {
                int base = (aRow + mtl * 16) * LDA + ks * 8 + kCol;
                a[mtl][0] = __float_as_uint(As[base]);
                a[mtl][1] = __float_as_uint(As[base + 8 * LDA]);
                a[mtl][2] = __float_as_uint(As[base + 4]);
                a[mtl][3] = __float_as_uint(As[base + 8 * LDA + 4]);
            }
#pragma unroll
            for (int nt = 0; nt < 4; nt++) {
                int base = (bRow + nt * 8) * LDA + ks * 8 + kCol;
                b[nt][0] = __float_as_uint(Bs[base]);
                b[nt][1] = __float_as_uint(Bs[base + 4]);
            }
#pragma unroll
            for (int mtl = 0; mtl < 4; mtl++)
#pragma unroll
                for (int nt = 0; nt < 4; nt++)
                    mma_tf32(c[mtl][nt], a[mtl], b[nt]);
        }
        __syncthreads();
    }

    // ---- epilogue: scatter to original token rows ----
    const int colBase = n0 + wn * 32 + 2 * (ln & 3);
#pragma unroll
    for (int mtl = 0; mtl < 4; mtl++) {
        int r0 = wm * 64 + mtl * 16 + (ln >> 2);
        int tok0 = rowTok[r0];
        int tok1 = rowTok[r0 + 8];
        if (tok0 >= 0) {
            float* po = out + (size_t)tok0 * OUTF + colBase;
#pragma unroll
            for (int nt = 0; nt < 4; nt++)
                *(float2*)(po + nt * 8) = make_float2(c[mtl][nt][0], c[mtl][nt][1]);
        }
        if (tok1 >= 0) {
            float* po = out + (size_t)tok1 * OUTF + colBase;
#pragma unroll
            for (int nt = 0; nt < 4; nt++)
                *(float2*)(po + nt * 8) = make_float2(c[mtl][nt][2], c[mtl][nt][3]);
        }
    }
}

extern "C" void kernel_launch(void* const* d_in, const int* in_sizes, int n_in,
                              void* d_out, int out_size)
{
    const float* x    = (const float*)d_in[0];
    const int*   gate = (const int*)d_in[1];
    const float* w    = (const float*)d_in[2];
    float*       out  = (float*)d_out;

    cudaFuncSetAttribute(k_gemm, cudaFuncAttributeMaxDynamicSharedMemorySize, SMEM_BYTES);

    k_init<<<1, 32>>>();
    k_hist<<<NTOK / 256, 256>>>(gate);
    k_scan<<<1, 32>>>();
    k_scatter<<<NTOK / 256, 256>>>(gate);
    k_cvtx<<<NTOK * INF / 1024, 256>>>(x);

    dim3 grid(MAXMT, OUTF / BN);   // 48 x 16
    k_gemm<<<grid, 256, SMEM_BYTES>>>(w, out);
}

// round 4
// speedup vs baseline: 4.9776x; 1.1333x over previous
#include <cuda_runtime.h>
#include <cstdint>

#define NE    16
#define NTOK  4096
#define INF   1024
#define OUTF  2048
#define BM    128
#define BN    128
#define BK    32
#define NKI   (INF / BK)          // 32 k-chunks
#define MAXMT (NTOK / BM + NE)    // 48 worst-case m-tiles
#define LDA   36                  // smem row stride in floats (32 + 4 pad)

// ---- device scratch ----
__device__ int   g_off[NE + 1];
__device__ int   g_sorted[NTOK];
__device__ int   g_tile[NE + 1];
__device__ float g_xt[NTOK * INF];   // x rounded to tf32 (16MB)

// ---- fused routing: hist + scan + scatter in one block ----
__global__ __launch_bounds__(1024) void k_route(const int* __restrict__ gate) {
    __shared__ int sc[NE];
    __shared__ int sfill[NE];
    const int tid = threadIdx.x;
    if (tid < NE) sc[tid] = 0;
    __syncthreads();
    for (int t = tid; t < NTOK; t += 1024) atomicAdd(&sc[gate[t]], 1);
    __syncthreads();
    if (tid == 0) {
        int s = 0, ts = 0;
        for (int e = 0; e < NE; e++) {
            g_off[e] = s; sfill[e] = s; g_tile[e] = ts;
            int c = sc[e];
            s += c; ts += (c + BM - 1) / BM;
        }
        g_off[NE] = s; g_tile[NE] = ts;
    }
    __syncthreads();
    for (int t = tid; t < NTOK; t += 1024) {
        int p = atomicAdd(&sfill[gate[t]], 1);
        g_sorted[p] = t;
    }
}

// ---- x -> tf32 (rounded) once ----
__device__ __forceinline__ uint32_t f2tf32(float f) {
    uint32_t r;
    asm("cvt.rna.tf32.f32 %0, %1;" : "=r"(r) : "f"(f));
    return r;
}
__global__ void k_cvtx(const float* __restrict__ x) {
    int i = (blockIdx.x * 256 + threadIdx.x) * 4;
    float4 v = *(const float4*)(x + i);
    uint4 t;
    t.x = f2tf32(v.x); t.y = f2tf32(v.y);
    t.z = f2tf32(v.z); t.w = f2tf32(v.w);
    *(uint4*)(g_xt + i) = t;
}

// ---- helpers ----
__device__ __forceinline__ uint32_t smem_u32(const void* p) {
    uint32_t a;
    asm("{ .reg .u64 t; cvta.to.shared.u64 t, %1; cvt.u32.u64 %0, t; }" : "=r"(a) : "l"(p));
    return a;
}
__device__ __forceinline__ void cp16(uint32_t dst, const void* src, uint32_t srcsz) {
    asm volatile("cp.async.ca.shared.global [%0], [%1], 16, %2;"
                 :: "r"(dst), "l"(src), "r"(srcsz) : "memory");
}
#define CP_COMMIT() asm volatile("cp.async.commit_group;" ::: "memory")
#define CP_WAIT(n)  asm volatile("cp.async.wait_group %0;" :: "n"(n) : "memory")

__device__ __forceinline__ void mma_tf32(float c[4], const uint32_t a[4], const uint32_t b[2]) {
    asm volatile(
        "mma.sync.aligned.m16n8k8.row.col.f32.tf32.tf32.f32 "
        "{%0,%1,%2,%3}, {%4,%5,%6,%7}, {%8,%9}, {%0,%1,%2,%3};"
        : "+f"(c[0]), "+f"(c[1]), "+f"(c[2]), "+f"(c[3])
        : "r"(a[0]), "r"(a[1]), "r"(a[2]), "r"(a[3]), "r"(b[0]), "r"(b[1]));
}
__device__ __forceinline__ void ldsm_x4(uint32_t r[4], uint32_t addr) {
    asm volatile("ldmatrix.sync.aligned.m8n8.x4.shared.b16 {%0,%1,%2,%3}, [%4];"
                 : "=r"(r[0]), "=r"(r[1]), "=r"(r[2]), "=r"(r[3]) : "r"(addr));
}
__device__ __forceinline__ void ldsm_x2(uint32_t r[2], uint32_t addr) {
    asm volatile("ldmatrix.sync.aligned.m8n8.x2.shared.b16 {%0,%1}, [%2];"
                 : "=r"(r[0]), "=r"(r[1]) : "r"(addr));
}

// SMEM (floats): A at buf*9216, B at 4608 + buf*9216; rowTok after
#define SM_FLOATS  18432
#define SMEM_BYTES (SM_FLOATS * 4 + 512)
#define BUF_BYTES  (9216 * 4)

// ---- grouped GEMM: out[tok, n] = x[tok,:] . W[e, n, :] ----
__global__ __launch_bounds__(256, 2) void k_gemm(
    const float* __restrict__ w,
    float* __restrict__ out)
{
    const int mt = blockIdx.x;
    if (mt >= g_tile[NE]) return;
    const int n0 = blockIdx.y * BN;

    extern __shared__ float smf[];
    int* rowTok = (int*)(smf + SM_FLOATS);

    const int tid = threadIdx.x;
    const int wid = tid >> 5;
    const int ln  = tid & 31;

    int e = 0;
#pragma unroll
    for (int i = 1; i < NE; i++) e += (mt >= g_tile[i]);
    const int seg_start = g_off[e];
    const int seg_cnt   = g_off[e + 1] - seg_start;
    const int m0        = (mt - g_tile[e]) * BM;

    if (tid < BM) {
        int idx = m0 + tid;
        rowTok[tid] = (idx < seg_cnt) ? g_sorted[seg_start + idx] : -1;
    }
    __syncthreads();

    // ---- loader: thread -> rows (tid>>3)+32i, 16B unit (tid&7) ----
    const int lr = tid >> 3;
    const int lq = tid & 7;
    const float* wbase = w + (size_t)e * OUTF * INF;
    int ltok[4];
    const float* asrc[4];
    const float* bsrc[4];
#pragma unroll
    for (int i = 0; i < 4; i++) {
        int r = lr + 32 * i;
        ltok[i] = rowTok[r];
        asrc[i] = g_xt + (size_t)((ltok[i] < 0) ? 0 : ltok[i]) * INF + lq * 4;
        bsrc[i] = wbase + (size_t)(n0 + r) * INF + lq * 4;
    }
    const uint32_t sbase = smem_u32(smf);
    uint32_t adst[4], bdst[4];
#pragma unroll
    for (int i = 0; i < 4; i++) {
        adst[i] = sbase + ((lr + 32 * i) * LDA + lq * 4) * 4;
        bdst[i] = sbase + (4608 + (lr + 32 * i) * LDA + lq * 4) * 4;
    }

    // ---- compute setup: warp (wm, wn) owns 64m x 32n ----
    const int wm = wid >> 2;
    const int wn = wid & 3;
    // ldmatrix lane addresses (byte offsets from smem base, buffer 0)
    // A matrix order per x4: (r,k),(r+8,k),(r,k+4),(r+8,k+4)
    const int amat = ln >> 3;          // 0..3
    const int arow = wm * 64 + ((amat & 1) << 3) + (ln & 7);
    const uint32_t aOff0 = (uint32_t)((arow * LDA + (amat >> 1) * 4) * 4);
    // B x2: matrices (k0..3), (k4..7); lanes 0..15 supply addrs
    const int bmat = (ln >> 3) & 1;
    const int brow = wn * 32 + (ln & 7);
    const uint32_t bOff0 = (uint32_t)(((4608 + brow * LDA) + bmat * 4) * 4);

    float c[4][4][4];
#pragma unroll
    for (int i = 0; i < 4; i++)
#pragma unroll
        for (int j = 0; j < 4; j++) {
            c[i][j][0] = 0.f; c[i][j][1] = 0.f; c[i][j][2] = 0.f; c[i][j][3] = 0.f;
        }

    // prologue: chunk 0 -> buffer 0
#pragma unroll
    for (int i = 0; i < 4; i++) {
        cp16(adst[i], asrc[i], ltok[i] < 0 ? 0u : 16u);
        cp16(bdst[i], bsrc[i], 16u);
    }
    CP_COMMIT();

    for (int it = 0; it < NKI; it++) {
        const int cbuf = it & 1;
        if (it + 1 < NKI) {
            const uint32_t nbo = (uint32_t)(((it + 1) & 1) * BUF_BYTES);
            const int koff = (it + 1) * BK;
#pragma unroll
            for (int i = 0; i < 4; i++) {
                cp16(adst[i] + nbo, asrc[i] + koff, ltok[i] < 0 ? 0u : 16u);
                cp16(bdst[i] + nbo, bsrc[i] + koff, 16u);
            }
            CP_COMMIT();
            CP_WAIT(1);
        } else {
            CP_WAIT(0);
        }
        __syncthreads();

        const uint32_t aB = sbase + cbuf * BUF_BYTES + aOff0;
        const uint32_t bB = sbase + cbuf * BUF_BYTES + bOff0;

#pragma unroll
        for (int ks = 0; ks < 4; ks++) {
            uint32_t a[4][4], b[4][2];
#pragma unroll
            for (int mtl = 0; mtl < 4; mtl++)
                ldsm_x4(a[mtl], aB + (mtl * 16 * LDA + ks * 8) * 4);
#pragma unroll
            for (int nt = 0; nt < 4; nt++)
                ldsm_x2(b[nt], bB + (nt * 8 * LDA + ks * 8) * 4);
#pragma unroll
            for (int mtl = 0; mtl < 4; mtl++)
#pragma unroll
                for (int nt = 0; nt < 4; nt++)
                    mma_tf32(c[mtl][nt], a[mtl], b[nt]);
        }
        __syncthreads();
    }

    // ---- epilogue: scatter rows to original tokens ----
    const int colBase = n0 + wn * 32 + 2 * (ln & 3);
#pragma unroll
    for (int mtl = 0; mtl < 4; mtl++) {
        int r0 = wm * 64 + mtl * 16 + (ln >> 2);
        int tok0 = rowTok[r0];
        int tok1 = rowTok[r0 + 8];
        if (tok0 >= 0) {
            float* po = out + (size_t)tok0 * OUTF + colBase;
#pragma unroll
            for (int nt = 0; nt < 4; nt++)
                *(float2*)(po + nt * 8) = make_float2(c[mtl][nt][0], c[mtl][nt][1]);
        }
        if (tok1 >= 0) {
            float* po = out + (size_t)tok1 * OUTF + colBase;
#pragma unroll
            for (int nt = 0; nt < 4; nt++)
                *(float2*)(po + nt * 8) = make_float2(c[mtl][nt][2], c[mtl][nt][3]);
        }
    }
}

extern "C" void kernel_launch(void* const* d_in, const int* in_sizes, int n_in,
                              void* d_out, int out_size)
{
    const float* x    = (const float*)d_in[0];
    const int*   gate = (const int*)d_in[1];
    const float* w    = (const float*)d_in[2];
    float*       out  = (float*)d_out;

    cudaFuncSetAttribute(k_gemm, cudaFuncAttributeMaxDynamicSharedMemorySize, SMEM_BYTES);

    k_cvtx<<<NTOK * INF / 1024, 256>>>(x);
    k_route<<<1, 1024>>>(gate);

    dim3 grid(MAXMT, OUTF / BN);   // 48 x 16
    k_gemm<<<grid, 256, SMEM_BYTES>>>(w, out);
}